// round 4
// baseline (speedup 1.0000x reference)
#include <cuda_runtime.h>
#include <math.h>

#define NN 100000
#define EE 1600000
#define CC 128
#define HH 64
#define GG 512

// ---------------- scratch (device globals: allocation-free) ----------------
__device__ float4 g_agg1[NN * (CC / 4)];   // zeroed only at kept rows
__device__ float4 g_out1[NN * (HH / 4)];   // written only at kept rows
__device__ float4 g_agg2[NN * (HH / 4)];   // zeroed only at kept rows
__device__ float g_raw[NN];
__device__ float g_score[NN];
__device__ unsigned char g_mask[NN];
__device__ float g_klval[GG];
__device__ float g_cntval[GG];
__device__ float g_go[GG * HH];
__device__ int g_kept[NN];
__device__ int g_elist[EE];
__device__ int g_nkept;
__device__ int g_n2;

// ---------------- helpers ----------------
__device__ __forceinline__ void red_add_v4(float4* a, float4 v) {
    asm volatile("red.global.add.v4.f32 [%0], {%1,%2,%3,%4};"
                 :: "l"(a), "f"(v.x), "f"(v.y), "f"(v.z), "f"(v.w) : "memory");
}

// ---------------- kernels ----------------

// raw[n] = dot(x[n], pool_w). One warp per node, fully coalesced float4.
// Also resets the global counters (consumed only by later launches).
__global__ void k_raw(const float4* __restrict__ x4, const float4* __restrict__ pw4) {
    int gt = blockIdx.x * blockDim.x + threadIdx.x;
    if (gt == 0) { g_nkept = 0; g_n2 = 0; }
    int n = gt >> 5;
    int lane = gt & 31;
    if (n >= NN) return;
    float4 v = x4[n * 32 + lane];
    float4 w = pw4[lane];
    float s = v.x * w.x + v.y * w.y + v.z * w.z + v.w * w.w;
    #pragma unroll
    for (int o = 16; o; o >>= 1) s += __shfl_down_sync(0xffffffffu, s, o);
    if (lane == 0) g_raw[n] = s;
}

// One block per graph: segment softmax, mask, KL, cnt, kept-list, agg zeroing.
// batch is sorted, so each graph's nodes are a contiguous range found by binary search.
__global__ void k_soft(const int* __restrict__ batch, const float* __restrict__ attn) {
    int b = blockIdx.x;
    int t = threadIdx.x;
    __shared__ int s_se[2];
    __shared__ float red[256];
    if (t < 2) {
        int target = b + t;
        int lo = 0, hi = NN;
        while (lo < hi) { int mid = (lo + hi) >> 1; if (batch[mid] < target) lo = mid + 1; else hi = mid; }
        s_se[t] = lo;
    }
    for (int k = t; k < HH; k += 256) g_go[b * HH + k] = 0.f;
    __syncthreads();
    int start = s_se[0], end = s_se[1];

    // pass 1: max
    float m = -INFINITY;
    for (int i = start + t; i < end; i += 256) m = fmaxf(m, g_raw[i]);
    red[t] = m; __syncthreads();
    for (int o = 128; o; o >>= 1) { if (t < o) red[t] = fmaxf(red[t], red[t + o]); __syncthreads(); }
    m = red[0]; __syncthreads();

    // pass 2: exp + sum
    float sum = 0.f;
    for (int i = start + t; i < end; i += 256) {
        float e = expf(g_raw[i] - m);
        g_score[i] = e;
        sum += e;
    }
    red[t] = sum; __syncthreads();
    for (int o = 128; o; o >>= 1) { if (t < o) red[t] += red[t + o]; __syncthreads(); }
    float z = red[0]; __syncthreads();

    // pass 3: normalize + smax
    float smax = 0.f;
    for (int i = start + t; i < end; i += 256) {
        float s = g_score[i] / z;
        g_score[i] = s;
        smax = fmaxf(smax, s);
    }
    red[t] = smax; __syncthreads();
    for (int o = 128; o; o >>= 1) { if (t < o) red[t] = fmaxf(red[t], red[t + o]); __syncthreads(); }
    smax = red[0]; __syncthreads();

    float thresh = fminf(smax - 1e-7f, 0.05f);

    // pass 4: mask, KL, cnt, kept-list append, zero agg rows of kept nodes
    float kl = 0.f, cnt = 0.f;
    for (int i = start + t; i < end; i += 256) {
        float s = g_score[i];
        bool keep = s > thresh;
        g_mask[i] = keep ? 1 : 0;
        if (keep) {
            cnt += 1.f;
            float a = attn[i];
            kl += a * (logf(a) - logf(s + 1e-14f));
            int p = atomicAdd(&g_nkept, 1);
            g_kept[p] = i;
            float4 zz = make_float4(0.f, 0.f, 0.f, 0.f);
            float4* a1 = &g_agg1[(size_t)i * 32];
            #pragma unroll
            for (int q = 0; q < 32; q++) a1[q] = zz;
            float4* a2 = &g_agg2[(size_t)i * 16];
            #pragma unroll
            for (int q = 0; q < 16; q++) a2[q] = zz;
        }
    }
    red[t] = kl; __syncthreads();
    for (int o = 128; o; o >>= 1) { if (t < o) red[t] += red[t + o]; __syncthreads(); }
    if (t == 0) g_klval[b] = red[0];
    __syncthreads();
    red[t] = cnt; __syncthreads();
    for (int o = 128; o; o >>= 1) { if (t < o) red[t] += red[t + o]; __syncthreads(); }
    if (t == 0) g_cntval[b] = red[0];
}

// Single edge scan, vectorized: each thread handles 4 edges via one int4 dst load.
// One block = 256 threads * 4 edges = 1024 edges (grid sized to match!).
// Scatter-1 for dst-kept edges (inline), and emit both-kept edge list for scatter-2.
#define EPB 1024   // edges per block
__global__ void k_edges(const int* __restrict__ ei, const float4* __restrict__ x4) {
    __shared__ int list[EPB];
    __shared__ int scnt;
    if (threadIdx.x == 0) scnt = 0;
    __syncthreads();
    int q = blockIdx.x * 256 + threadIdx.x;   // int4 index into dst array
    if (q < EE / 4) {
        int4 d4 = ((const int4*)(ei + EE))[q];
        int e0 = q * 4;
        int dd[4] = {d4.x, d4.y, d4.z, d4.w};
        #pragma unroll
        for (int k = 0; k < 4; k++) {
            int d = dd[k];
            if (g_mask[d]) {
                int e = e0 + k;
                int p = atomicAdd(&scnt, 1);
                list[p] = e;
                int s = ei[e];
                if (g_mask[s]) {
                    int w = atomicAdd(&g_n2, 1);
                    g_elist[w] = e;
                }
            }
        }
    }
    __syncthreads();
    int nk = scnt;
    int wid = threadIdx.x >> 5;
    int lane = threadIdx.x & 31;
    for (int i = wid; i < nk; i += 8) {
        int ee = list[i];
        int s = ei[ee];
        int d = ei[EE + ee];
        red_add_v4(&g_agg1[(size_t)d * 32 + lane], x4[(size_t)s * 32 + lane]);
    }
}

// GIN1 MLP only for kept nodes (grid-stride over device-side kept list).
__global__ void k_gin1(const float* __restrict__ x,
                       const float* __restrict__ W1, const float* __restrict__ b1,
                       const float* __restrict__ W2, const float* __restrict__ b2) {
    __shared__ float sh[4][CC];
    __shared__ float st[4][HH];
    int local = threadIdx.x >> 6;
    int j = threadIdx.x & 63;
    int nk = g_nkept;
    for (int base = blockIdx.x * 4; base < nk; base += gridDim.x * 4) {
        int idx = base + local;
        int n = (idx < nk) ? g_kept[idx] : -1;
        if (n >= 0) {
            const float* a1 = (const float*)&g_agg1[(size_t)n * 32];
            for (int k = j; k < CC; k += 64) sh[local][k] = x[(size_t)n * CC + k] + a1[k];
        }
        __syncthreads();
        if (n >= 0) {
            float tt = b1[j];
            #pragma unroll 8
            for (int k = 0; k < CC; k++) tt = fmaf(sh[local][k], __ldg(&W1[k * HH + j]), tt);
            st[local][j] = fmaxf(tt, 0.f);
        }
        __syncthreads();
        if (n >= 0) {
            float o = b2[j];
            #pragma unroll 8
            for (int k = 0; k < HH; k++) o = fmaf(st[local][k], __ldg(&W2[k * HH + j]), o);
            o = fmaxf(o, 0.f);
            ((float*)&g_out1[(size_t)n * 16])[j] = o * g_score[n];
        }
        __syncthreads();
    }
}

// Scatter 2: only over the compacted both-kept edge list (tiny).
__global__ void k_scat2(const int* __restrict__ ei) {
    int n2 = g_n2;
    int gw = (blockIdx.x * blockDim.x + threadIdx.x) >> 5;
    int lane = threadIdx.x & 31;
    int nw = (gridDim.x * blockDim.x) >> 5;
    for (int i = gw; i < n2; i += nw) {
        int e = g_elist[i];
        int s = ei[e];
        int d = ei[EE + e];
        if (lane < 16)
            red_add_v4(&g_agg2[(size_t)d * 16 + lane], g_out1[(size_t)s * 16 + lane]);
    }
}

// GIN2 MLP for kept nodes + atomic accumulate into graph_out.
__global__ void k_gin2(const int* __restrict__ batch,
                       const float* __restrict__ W3, const float* __restrict__ b3,
                       const float* __restrict__ W4, const float* __restrict__ b4) {
    __shared__ float sh[4][HH];
    __shared__ float st[4][HH];
    int local = threadIdx.x >> 6;
    int j = threadIdx.x & 63;
    int nk = g_nkept;
    for (int base = blockIdx.x * 4; base < nk; base += gridDim.x * 4) {
        int idx = base + local;
        int n = (idx < nk) ? g_kept[idx] : -1;
        if (n >= 0) {
            const float* o1 = (const float*)&g_out1[(size_t)n * 16];
            const float* a2 = (const float*)&g_agg2[(size_t)n * 16];
            sh[local][j] = o1[j] + a2[j];
        }
        __syncthreads();
        if (n >= 0) {
            float tt = b3[j];
            #pragma unroll 8
            for (int k = 0; k < HH; k++) tt = fmaf(sh[local][k], __ldg(&W3[k * HH + j]), tt);
            st[local][j] = fmaxf(tt, 0.f);
        }
        __syncthreads();
        if (n >= 0) {
            float o = b4[j];
            #pragma unroll 8
            for (int k = 0; k < HH; k++) o = fmaf(st[local][k], __ldg(&W4[k * HH + j]), o);
            o = fmaxf(o, 0.f);
            atomicAdd(&g_go[batch[n] * HH + j], o);
        }
        __syncthreads();
    }
}

// Final: pred, attn_loss, ratio -> d_out
__global__ void k_final(const float* __restrict__ Wl, const float* __restrict__ bl,
                        float* __restrict__ out) {
    int g = threadIdx.x + blockIdx.x * blockDim.x;
    if (g < GG) {
        float p = bl[0];
        #pragma unroll 8
        for (int k = 0; k < HH; k++) p = fmaf(g_go[g * HH + k], Wl[k], p);
        out[g] = p;
        out[GG + g] = g_klval[g] / fmaxf(g_cntval[g], 1.0f);
    }
    if (g == 0) out[2 * GG] = (float)g_nkept / (float)NN;
}

// ---------------- launch ----------------
extern "C" void kernel_launch(void* const* d_in, const int* in_sizes, int n_in,
                              void* d_out, int out_size) {
    const float* x      = (const float*)d_in[0];
    const int*   ei     = (const int*)d_in[1];
    const int*   batch  = (const int*)d_in[2];
    const float* attn   = (const float*)d_in[3];
    const float* W1     = (const float*)d_in[4];
    const float* b1     = (const float*)d_in[5];
    const float* W2     = (const float*)d_in[6];
    const float* b2     = (const float*)d_in[7];
    const float* pool_w = (const float*)d_in[8];
    const float* W3     = (const float*)d_in[9];
    const float* b3     = (const float*)d_in[10];
    const float* W4     = (const float*)d_in[11];
    const float* b4     = (const float*)d_in[12];
    const float* Wl     = (const float*)d_in[13];
    const float* bl     = (const float*)d_in[14];
    float* out = (float*)d_out;

    k_raw<<<(NN * 32 + 255) / 256, 256>>>((const float4*)x, (const float4*)pool_w);
    k_soft<<<GG, 256>>>(batch, attn);
    k_edges<<<(EE + EPB - 1) / EPB, 256>>>(ei, (const float4*)x);
    k_gin1<<<128, 256>>>(x, W1, b1, W2, b2);
    k_scat2<<<16, 256>>>(ei);
    k_gin2<<<128, 256>>>(batch, W3, b3, W4, b4);
    k_final<<<2, 256>>>(Wl, bl, out);
}

// round 5
// speedup vs baseline: 1.2210x; 1.2210x over previous
#include <cuda_runtime.h>
#include <math.h>

#define NN 100000
#define EE 1600000
#define CC 128
#define HH 64
#define GG 512

// ---------------- scratch (device globals: allocation-free) ----------------
__device__ float4 g_agg1[NN * (CC / 4)];   // zeroed only at kept rows
__device__ float4 g_out1[NN * (HH / 4)];   // written only at kept rows
__device__ float4 g_agg2[NN * (HH / 4)];   // zeroed only at kept rows
__device__ float g_raw[NN];
__device__ float g_score[NN];
__device__ unsigned char g_mask[NN];
__device__ float g_klval[GG];
__device__ float g_cntval[GG];
__device__ float g_go[GG * HH];
__device__ int g_kept[NN];
__device__ int g_elist[EE];
__device__ int g_nkept;
__device__ int g_n2;

// ---------------- helpers ----------------
__device__ __forceinline__ void red_add_v4(float4* a, float4 v) {
    asm volatile("red.global.add.v4.f32 [%0], {%1,%2,%3,%4};"
                 :: "l"(a), "f"(v.x), "f"(v.y), "f"(v.z), "f"(v.w) : "memory");
}

// ---------------- kernels ----------------

// raw[n] = dot(x[n], pool_w). One warp per node, fully coalesced float4.
// Also resets the global counters (consumed only by later launches).
__global__ void k_raw(const float4* __restrict__ x4, const float4* __restrict__ pw4) {
    int gt = blockIdx.x * blockDim.x + threadIdx.x;
    if (gt == 0) { g_nkept = 0; g_n2 = 0; }
    int n = gt >> 5;
    int lane = gt & 31;
    if (n >= NN) return;
    float4 v = x4[n * 32 + lane];
    float4 w = pw4[lane];
    float s = v.x * w.x + v.y * w.y + v.z * w.z + v.w * w.w;
    #pragma unroll
    for (int o = 16; o; o >>= 1) s += __shfl_down_sync(0xffffffffu, s, o);
    if (lane == 0) g_raw[n] = s;
}

// One block per graph: segment softmax, mask, KL, cnt, kept-list, agg zeroing.
// batch is sorted, so each graph's nodes are a contiguous range found by binary search.
__global__ void k_soft(const int* __restrict__ batch, const float* __restrict__ attn) {
    int b = blockIdx.x;
    int t = threadIdx.x;
    __shared__ int s_se[2];
    __shared__ float red[256];
    if (t < 2) {
        int target = b + t;
        int lo = 0, hi = NN;
        while (lo < hi) { int mid = (lo + hi) >> 1; if (batch[mid] < target) lo = mid + 1; else hi = mid; }
        s_se[t] = lo;
    }
    for (int k = t; k < HH; k += 256) g_go[b * HH + k] = 0.f;
    __syncthreads();
    int start = s_se[0], end = s_se[1];

    float m = -INFINITY;
    for (int i = start + t; i < end; i += 256) m = fmaxf(m, g_raw[i]);
    red[t] = m; __syncthreads();
    for (int o = 128; o; o >>= 1) { if (t < o) red[t] = fmaxf(red[t], red[t + o]); __syncthreads(); }
    m = red[0]; __syncthreads();

    float sum = 0.f;
    for (int i = start + t; i < end; i += 256) {
        float e = expf(g_raw[i] - m);
        g_score[i] = e;
        sum += e;
    }
    red[t] = sum; __syncthreads();
    for (int o = 128; o; o >>= 1) { if (t < o) red[t] += red[t + o]; __syncthreads(); }
    float z = red[0]; __syncthreads();

    float smax = 0.f;
    for (int i = start + t; i < end; i += 256) {
        float s = g_score[i] / z;
        g_score[i] = s;
        smax = fmaxf(smax, s);
    }
    red[t] = smax; __syncthreads();
    for (int o = 128; o; o >>= 1) { if (t < o) red[t] = fmaxf(red[t], red[t + o]); __syncthreads(); }
    smax = red[0]; __syncthreads();

    float thresh = fminf(smax - 1e-7f, 0.05f);

    float kl = 0.f, cnt = 0.f;
    for (int i = start + t; i < end; i += 256) {
        float s = g_score[i];
        bool keep = s > thresh;
        g_mask[i] = keep ? 1 : 0;
        if (keep) {
            cnt += 1.f;
            float a = attn[i];
            kl += a * (logf(a) - logf(s + 1e-14f));
            int p = atomicAdd(&g_nkept, 1);
            g_kept[p] = i;
            float4 zz = make_float4(0.f, 0.f, 0.f, 0.f);
            float4* a1 = &g_agg1[(size_t)i * 32];
            #pragma unroll
            for (int q = 0; q < 32; q++) a1[q] = zz;
            float4* a2 = &g_agg2[(size_t)i * 16];
            #pragma unroll
            for (int q = 0; q < 16; q++) a2[q] = zz;
        }
    }
    red[t] = kl; __syncthreads();
    for (int o = 128; o; o >>= 1) { if (t < o) red[t] += red[t + o]; __syncthreads(); }
    if (t == 0) g_klval[b] = red[0];
    __syncthreads();
    red[t] = cnt; __syncthreads();
    for (int o = 128; o; o >>= 1) { if (t < o) red[t] += red[t + o]; __syncthreads(); }
    if (t == 0) g_cntval[b] = red[0];
}

// Single edge scan, vectorized: each thread handles 4 edges via one int4 dst load.
// One block = 256 threads * 4 edges = 1024 edges.
#define EPB 1024
__global__ void k_edges(const int* __restrict__ ei, const float4* __restrict__ x4) {
    __shared__ int list[EPB];
    __shared__ int scnt;
    if (threadIdx.x == 0) scnt = 0;
    __syncthreads();
    int q = blockIdx.x * 256 + threadIdx.x;
    if (q < EE / 4) {
        int4 d4 = ((const int4*)(ei + EE))[q];
        int e0 = q * 4;
        int dd[4] = {d4.x, d4.y, d4.z, d4.w};
        #pragma unroll
        for (int k = 0; k < 4; k++) {
            int d = dd[k];
            if (g_mask[d]) {
                int e = e0 + k;
                int p = atomicAdd(&scnt, 1);
                list[p] = e;
                int s = ei[e];
                if (g_mask[s]) {
                    int w = atomicAdd(&g_n2, 1);
                    g_elist[w] = e;
                }
            }
        }
    }
    __syncthreads();
    int nk = scnt;
    int wid = threadIdx.x >> 5;
    int lane = threadIdx.x & 31;
    for (int i = wid; i < nk; i += 8) {
        int ee = list[i];
        int s = ei[ee];
        int d = ei[EE + ee];
        red_add_v4(&g_agg1[(size_t)d * 32 + lane], x4[(size_t)s * 32 + lane]);
    }
}

// GIN1 MLP for kept nodes. W1 (32KB) + W2 (16KB) staged in dynamic shared memory
// via cooperative float4 loads (full MLP, latency hidden once), compute from LDS.
__global__ void k_gin1(const float* __restrict__ x,
                       const float* __restrict__ W1, const float* __restrict__ b1,
                       const float* __restrict__ W2, const float* __restrict__ b2) {
    extern __shared__ float dsm[];
    float* sW1 = dsm;                    // 128*64 = 8192 floats
    float* sW2 = dsm + CC * HH;          // 64*64  = 4096 floats
    float* sh  = dsm + CC * HH + HH * HH;        // 4*128
    float* st  = sh + 4 * CC;                    // 4*64
    int tid = threadIdx.x;

    // cooperative staging of W1, W2 (coalesced float4, deep MLP)
    const float4* w14 = (const float4*)W1;
    #pragma unroll
    for (int i = tid; i < (CC * HH) / 4; i += 256) ((float4*)sW1)[i] = w14[i];
    const float4* w24 = (const float4*)W2;
    #pragma unroll
    for (int i = tid; i < (HH * HH) / 4; i += 256) ((float4*)sW2)[i] = w24[i];

    int local = tid >> 6;
    int j = tid & 63;
    float bb1 = b1[j];
    float bb2 = b2[j];
    int nk = g_nkept;
    __syncthreads();

    for (int base = blockIdx.x * 4; base < nk; base += gridDim.x * 4) {
        int idx = base + local;
        int n = (idx < nk) ? g_kept[idx] : -1;
        if (n >= 0) {
            const float* a1 = (const float*)&g_agg1[(size_t)n * 32];
            for (int k = j; k < CC; k += 64) sh[local * CC + k] = x[(size_t)n * CC + k] + a1[k];
        }
        __syncthreads();
        if (n >= 0) {
            float acc0 = bb1, acc1 = 0.f, acc2 = 0.f, acc3 = 0.f;
            #pragma unroll
            for (int k = 0; k < CC; k += 4) {
                acc0 = fmaf(sh[local * CC + k    ], sW1[(k    ) * HH + j], acc0);
                acc1 = fmaf(sh[local * CC + k + 1], sW1[(k + 1) * HH + j], acc1);
                acc2 = fmaf(sh[local * CC + k + 2], sW1[(k + 2) * HH + j], acc2);
                acc3 = fmaf(sh[local * CC + k + 3], sW1[(k + 3) * HH + j], acc3);
            }
            st[local * HH + j] = fmaxf((acc0 + acc1) + (acc2 + acc3), 0.f);
        }
        __syncthreads();
        if (n >= 0) {
            float acc0 = bb2, acc1 = 0.f, acc2 = 0.f, acc3 = 0.f;
            #pragma unroll
            for (int k = 0; k < HH; k += 4) {
                acc0 = fmaf(st[local * HH + k    ], sW2[(k    ) * HH + j], acc0);
                acc1 = fmaf(st[local * HH + k + 1], sW2[(k + 1) * HH + j], acc1);
                acc2 = fmaf(st[local * HH + k + 2], sW2[(k + 2) * HH + j], acc2);
                acc3 = fmaf(st[local * HH + k + 3], sW2[(k + 3) * HH + j], acc3);
            }
            float o = fmaxf((acc0 + acc1) + (acc2 + acc3), 0.f);
            ((float*)&g_out1[(size_t)n * 16])[j] = o * g_score[n];
        }
        __syncthreads();
    }
}

// Scatter 2: only over the compacted both-kept edge list (tiny).
__global__ void k_scat2(const int* __restrict__ ei) {
    int n2 = g_n2;
    int gw = (blockIdx.x * blockDim.x + threadIdx.x) >> 5;
    int lane = threadIdx.x & 31;
    int nw = (gridDim.x * blockDim.x) >> 5;
    for (int i = gw; i < n2; i += nw) {
        int e = g_elist[i];
        int s = ei[e];
        int d = ei[EE + e];
        if (lane < 16)
            red_add_v4(&g_agg2[(size_t)d * 16 + lane], g_out1[(size_t)s * 16 + lane]);
    }
}

// GIN2 MLP for kept nodes + atomic accumulate into graph_out.
// W3+W4 (32KB) staged in static shared memory.
__global__ void k_gin2(const int* __restrict__ batch,
                       const float* __restrict__ W3, const float* __restrict__ b3,
                       const float* __restrict__ W4, const float* __restrict__ b4) {
    __shared__ float sW3[HH * HH];
    __shared__ float sW4[HH * HH];
    __shared__ float sh[4 * HH];
    __shared__ float st[4 * HH];
    int tid = threadIdx.x;
    #pragma unroll
    for (int i = tid; i < (HH * HH) / 4; i += 256) ((float4*)sW3)[i] = ((const float4*)W3)[i];
    #pragma unroll
    for (int i = tid; i < (HH * HH) / 4; i += 256) ((float4*)sW4)[i] = ((const float4*)W4)[i];

    int local = tid >> 6;
    int j = tid & 63;
    float bb3 = b3[j];
    float bb4 = b4[j];
    int nk = g_nkept;
    __syncthreads();

    for (int base = blockIdx.x * 4; base < nk; base += gridDim.x * 4) {
        int idx = base + local;
        int n = (idx < nk) ? g_kept[idx] : -1;
        if (n >= 0) {
            const float* o1 = (const float*)&g_out1[(size_t)n * 16];
            const float* a2 = (const float*)&g_agg2[(size_t)n * 16];
            sh[local * HH + j] = o1[j] + a2[j];
        }
        __syncthreads();
        if (n >= 0) {
            float acc0 = bb3, acc1 = 0.f, acc2 = 0.f, acc3 = 0.f;
            #pragma unroll
            for (int k = 0; k < HH; k += 4) {
                acc0 = fmaf(sh[local * HH + k    ], sW3[(k    ) * HH + j], acc0);
                acc1 = fmaf(sh[local * HH + k + 1], sW3[(k + 1) * HH + j], acc1);
                acc2 = fmaf(sh[local * HH + k + 2], sW3[(k + 2) * HH + j], acc2);
                acc3 = fmaf(sh[local * HH + k + 3], sW3[(k + 3) * HH + j], acc3);
            }
            st[local * HH + j] = fmaxf((acc0 + acc1) + (acc2 + acc3), 0.f);
        }
        __syncthreads();
        if (n >= 0) {
            float acc0 = bb4, acc1 = 0.f, acc2 = 0.f, acc3 = 0.f;
            #pragma unroll
            for (int k = 0; k < HH; k += 4) {
                acc0 = fmaf(st[local * HH + k    ], sW4[(k    ) * HH + j], acc0);
                acc1 = fmaf(st[local * HH + k + 1], sW4[(k + 1) * HH + j], acc1);
                acc2 = fmaf(st[local * HH + k + 2], sW4[(k + 2) * HH + j], acc2);
                acc3 = fmaf(st[local * HH + k + 3], sW4[(k + 3) * HH + j], acc3);
            }
            float o = fmaxf((acc0 + acc1) + (acc2 + acc3), 0.f);
            atomicAdd(&g_go[batch[n] * HH + j], o);
        }
        __syncthreads();
    }
}

// Final: pred, attn_loss, ratio -> d_out
__global__ void k_final(const float* __restrict__ Wl, const float* __restrict__ bl,
                        float* __restrict__ out) {
    int g = threadIdx.x + blockIdx.x * blockDim.x;
    if (g < GG) {
        float p = bl[0];
        #pragma unroll 8
        for (int k = 0; k < HH; k++) p = fmaf(g_go[g * HH + k], Wl[k], p);
        out[g] = p;
        out[GG + g] = g_klval[g] / fmaxf(g_cntval[g], 1.0f);
    }
    if (g == 0) out[2 * GG] = (float)g_nkept / (float)NN;
}

// ---------------- launch ----------------
#define GIN1_SMEM ((CC * HH + HH * HH + 4 * CC + 4 * HH) * (int)sizeof(float))

extern "C" void kernel_launch(void* const* d_in, const int* in_sizes, int n_in,
                              void* d_out, int out_size) {
    const float* x      = (const float*)d_in[0];
    const int*   ei     = (const int*)d_in[1];
    const int*   batch  = (const int*)d_in[2];
    const float* attn   = (const float*)d_in[3];
    const float* W1     = (const float*)d_in[4];
    const float* b1     = (const float*)d_in[5];
    const float* W2     = (const float*)d_in[6];
    const float* b2     = (const float*)d_in[7];
    const float* pool_w = (const float*)d_in[8];
    const float* W3     = (const float*)d_in[9];
    const float* b3     = (const float*)d_in[10];
    const float* W4     = (const float*)d_in[11];
    const float* b4     = (const float*)d_in[12];
    const float* Wl     = (const float*)d_in[13];
    const float* bl     = (const float*)d_in[14];
    float* out = (float*)d_out;

    // idempotent per-call; not a stream op, safe under graph capture
    cudaFuncSetAttribute(k_gin1, cudaFuncAttributeMaxDynamicSharedMemorySize, GIN1_SMEM);

    k_raw<<<(NN * 32 + 255) / 256, 256>>>((const float4*)x, (const float4*)pool_w);
    k_soft<<<GG, 256>>>(batch, attn);
    k_edges<<<(EE + EPB - 1) / EPB, 256>>>(ei, (const float4*)x);
    k_gin1<<<128, 256, GIN1_SMEM>>>(x, W1, b1, W2, b2);
    k_scat2<<<16, 256>>>(ei);
    k_gin2<<<128, 256>>>(batch, W3, b3, W4, b4);
    k_final<<<2, 256>>>(Wl, bl, out);
}